// round 10
// baseline (speedup 1.0000x reference)
#include <cuda_runtime.h>
#include <math.h>
#include <stdint.h>

// Problem constants: B=64, T=1024, V=50000, D=256, Hh=256, H=512, K=12
#define NEGV (-10000.0f)

// ---------------- device scratch (no cudaMalloc allowed) ----------------
__device__ float    g_xz[134217728];   // [1024 t][2048 n][64 b]  gate preacts
__device__ float    g_hall[33554432];  // [64 b][1024 t][512]     all hidden states
__device__ float    g_hbuf[2][32768];  // ping-pong h [parity][dir*16384 + b*256 + u]
__device__ float    g_Wt[524288];      // [256 k][2048 n]  transposed input weights
__device__ float    g_bias[2048];      // bih+bhh, forward | backward
__device__ float    g_feats[786432];   // [64 b][1024 t][12 k]
__device__ int      g_flag[2][64];     // per-block step flags (release/acquire barrier)

// precise activations (fast-math variants flipped Viterbi argmax ties in R7)
__device__ __forceinline__ float sig_p(float x)  { return 1.f / (1.f + expf(-x)); }

// ---------------- prep: transpose Wih, fold biases, init h buffer ----------------
__global__ void prep_kernel(const float* __restrict__ Wih_f, const float* __restrict__ Wih_b,
                            const float* __restrict__ bih_f, const float* __restrict__ bhh_f,
                            const float* __restrict__ bih_b, const float* __restrict__ bhh_b,
                            const float* __restrict__ h0) {
    int i  = blockIdx.x * blockDim.x + threadIdx.x;
    int nt = gridDim.x * blockDim.x;
    for (int e = i; e < 524288; e += nt) {
        int k = e >> 11, n = e & 2047;
        g_Wt[e] = (n < 1024) ? Wih_f[n * 256 + k] : Wih_b[(n - 1024) * 256 + k];
    }
    if (i < 2048) g_bias[i] = (i < 1024) ? (bih_f[i] + bhh_f[i])
                                         : (bih_b[i - 1024] + bhh_b[i - 1024]);
    if (i < 32768) g_hbuf[0][i] = h0[i];   // h0 is [2][64][256] flat
    if (i < 128) g_flag[i >> 6][i & 63] = 0;
}

// ---------------- gather-SGEMM: xz = emb[sent] @ Wt + bias ----------------
// m is t-major: m = t*64 + b  (so epilogue stores to [t][n][b] are coalesced in b).
// 128x128x8 tile, 256 threads, 8x8 microtile with rows strided by 16. (R8-exact)
__global__ void __launch_bounds__(256) gemm_kernel(const int* __restrict__ sent,
                                                   const float* __restrict__ emb) {
    __shared__ float As[8][128];
    __shared__ float Bs[8][128];
    __shared__ int   idx[128];
    int tid = threadIdx.x;
    int m0 = blockIdx.y * 128;
    int n0 = blockIdx.x * 128;
    if (tid < 128) {
        int m = m0 + tid;                       // m = t*64 + b
        idx[tid] = sent[(m & 63) * 1024 + (m >> 6)];
    }
    __syncthreads();

    float acc[8][8];
#pragma unroll
    for (int i = 0; i < 8; i++)
#pragma unroll
        for (int j = 0; j < 8; j++) acc[i][j] = 0.f;

    int rbase = tid & 15, nty = tid >> 4;      // rows: rbase+16i ; cols: nty*8+j
    int ar = tid >> 1, akq = (tid & 1) * 4;    // A-tile load coords
    int bkr = tid >> 5, bnc = (tid & 31) * 4;  // B-tile load coords
    const float* arow = emb + (size_t)idx[ar] * 256;

    for (int kt = 0; kt < 256; kt += 8) {
        float4 av = *(const float4*)(arow + kt + akq);
        As[akq + 0][ar] = av.x; As[akq + 1][ar] = av.y;
        As[akq + 2][ar] = av.z; As[akq + 3][ar] = av.w;
        *(float4*)&Bs[bkr][bnc] =
            *(const float4*)&g_Wt[(size_t)(kt + bkr) * 2048 + n0 + bnc];
        __syncthreads();
#pragma unroll
        for (int k = 0; k < 8; k++) {
            float a[8];
#pragma unroll
            for (int i = 0; i < 8; i++) a[i] = As[k][rbase + 16 * i];
            float4 b0 = *(float4*)&Bs[k][nty * 8];
            float4 b1 = *(float4*)&Bs[k][nty * 8 + 4];
            float rb[8] = {b0.x, b0.y, b0.z, b0.w, b1.x, b1.y, b1.z, b1.w};
#pragma unroll
            for (int i = 0; i < 8; i++)
#pragma unroll
                for (int j = 0; j < 8; j++) acc[i][j] += a[i] * rb[j];
        }
        __syncthreads();
    }

#pragma unroll
    for (int i = 0; i < 8; i++) {
        int mm = m0 + rbase + 16 * i;
        int tt = mm >> 6, b = mm & 63;
#pragma unroll
        for (int j = 0; j < 8; j++) {
            int n = n0 + nty * 8 + j;
            g_xz[((size_t)tt * 2048 + n) * 64 + b] = acc[i][j] + g_bias[n];
        }
    }
}

// ---------------- persistent BiLSTM recurrence (W-stationary in registers) ----------------
// R8-exact compute; ONLY the grid barrier is changed: release-store of a per-block
// flag + 64-lane acquire-poll (replaces threadfence + serialized same-address atomics).
__global__ void __launch_bounds__(256, 1) lstm_kernel(const float* __restrict__ Whh_f,
                                                      const float* __restrict__ Whh_b,
                                                      const float* __restrict__ c0,
                                                      const int*   __restrict__ seq_lens) {
    __shared__ float z_s[1024];   // [warp][bb][row] = [8][8][16]

    int tid  = threadIdx.x;
    int w    = tid >> 5;
    int lane = tid & 31;
    int dir  = blockIdx.x >> 6;
    int ublk = blockIdx.x & 63;
    int kc   = lane & 15;
    int half = lane >> 4;
    int l3 = (lane >> 3) & 1, l2 = (lane >> 2) & 1, l1 = (lane >> 1) & 1;

    const float* Whh = dir ? Whh_b : Whh_f;

    // Load W slice into registers: Wv[rr][q] = Whh[row][q*64 + kc*4 .. +3]
    float4 Wv[8][4];
#pragma unroll
    for (int rr = 0; rr < 8; rr++) {
        int rl = half * 8 + rr;
        int g = rl >> 2, u = rl & 3;
        const float* wrow = Whh + ((size_t)(g * 256 + ublk * 4 + u)) * 256;
#pragma unroll
        for (int q = 0; q < 4; q++)
            Wv[rr][q] = *(const float4*)(wrow + q * 64 + kc * 4);
    }

    // Elementwise-phase identity: lane -> (bb, u) cell
    int bb_e = lane >> 2, u_e = lane & 3;
    int b_e  = w * 8 + bb_e;
    int ug_e = ublk * 4 + u_e;
    float c     = __ldg(&c0[dir * 16384 + b_e * 256 + ug_e]);
    float hprev = g_hbuf[0][dir * 16384 + b_e * 256 + ug_e];
    int   len   = __ldg(&seq_lens[b_e]);
    int  zrow   = half * 8 + ((lane >> 1) & 7);
    bool do_sts = ((lane & 1) == 0);
    float* zw   = z_s + w * 128 + bb_e * 16;

    for (int step = 0; step < 1024; step++) {
        int p = step & 1;
        int t = dir ? (1023 - step) : step;
        const float4* hsrc = (const float4*)(g_hbuf[p] + dir * 16384);

        // prefetch b = w*8
        float4 hv[4], hn4[4];
        {
            int bi = (w * 8) * 64;
#pragma unroll
            for (int q = 0; q < 4; q++) hv[q] = __ldcg(hsrc + bi + q * 16 + kc);
        }
#pragma unroll
        for (int bb = 0; bb < 8; bb++) {
            if (bb < 7) {
                int bi = (w * 8 + bb + 1) * 64;
#pragma unroll
                for (int q = 0; q < 4; q++) hn4[q] = __ldcg(hsrc + bi + q * 16 + kc);
            }
            float acc[8];
#pragma unroll
            for (int rr = 0; rr < 8; rr++) {
                float s = Wv[rr][0].x * hv[0].x;
                s += Wv[rr][0].y * hv[0].y; s += Wv[rr][0].z * hv[0].z; s += Wv[rr][0].w * hv[0].w;
                s += Wv[rr][1].x * hv[1].x; s += Wv[rr][1].y * hv[1].y;
                s += Wv[rr][1].z * hv[1].z; s += Wv[rr][1].w * hv[1].w;
                s += Wv[rr][2].x * hv[2].x; s += Wv[rr][2].y * hv[2].y;
                s += Wv[rr][2].z * hv[2].z; s += Wv[rr][2].w * hv[2].w;
                s += Wv[rr][3].x * hv[3].x; s += Wv[rr][3].y * hv[3].y;
                s += Wv[rr][3].z * hv[3].z; s += Wv[rr][3].w * hv[3].w;
                acc[rr] = s;
            }
            // register-halving butterfly reduction over k (lane bits 3..0)
#pragma unroll
            for (int j = 0; j < 4; j++) {
                float send = l3 ? acc[j] : acc[j + 4];
                float recv = __shfl_xor_sync(0xffffffffu, send, 8);
                acc[j] = (l3 ? acc[j + 4] : acc[j]) + recv;
            }
#pragma unroll
            for (int j = 0; j < 2; j++) {
                float send = l2 ? acc[j] : acc[j + 2];
                float recv = __shfl_xor_sync(0xffffffffu, send, 4);
                acc[j] = (l2 ? acc[j + 2] : acc[j]) + recv;
            }
            {
                float send = l1 ? acc[0] : acc[1];
                float recv = __shfl_xor_sync(0xffffffffu, send, 2);
                acc[0] = (l1 ? acc[1] : acc[0]) + recv;
            }
            acc[0] += __shfl_xor_sync(0xffffffffu, acc[0], 1);
            if (do_sts) z_s[w * 128 + bb * 16 + zrow] = acc[0];
#pragma unroll
            for (int q = 0; q < 4; q++) hv[q] = hn4[q];
        }
        __syncwarp();

        // elementwise: lane owns cell (b_e, u_e) — precise activations
        float zi = zw[0 + u_e], zf = zw[4 + u_e], zg = zw[8 + u_e], zo = zw[12 + u_e];
        const float* xzp = g_xz + ((size_t)t * 2048 + dir * 1024 + ug_e) * 64 + b_e;
        zi += __ldg(xzp);
        zf += __ldg(xzp + 16384);
        zg += __ldg(xzp + 32768);
        zo += __ldg(xzp + 49152);

        float ai = sig_p(zi), af = sig_p(zf), ag = tanhf(zg), ao = sig_p(zo);
        float c2 = af * c + ai * ag;
        float h2 = ao * tanhf(c2);

        bool m = (t < len);
        if (m) c = c2;
        float hn = m ? h2 : hprev;
        hprev = hn;

        g_hbuf[p ^ 1][dir * 16384 + b_e * 256 + ug_e] = hn;
        g_hall[((size_t)(b_e * 1024 + t)) * 512 + dir * 256 + ug_e] = hn;

        // grid barrier: block stores done -> release own flag; poll all 64 flags
        __syncthreads();
        if (tid == 0) {
            asm volatile("st.release.gpu.global.s32 [%0], %1;"
                         :: "l"(&g_flag[dir][ublk]), "r"(step + 1) : "memory");
        }
        if (tid < 64) {
            const int* fp = &g_flag[dir][tid];
            int v;
            do {
                asm volatile("ld.acquire.gpu.global.s32 %0, [%1];"
                             : "=r"(v) : "l"(fp) : "memory");
            } while (v <= step);
        }
        __syncthreads();
    }
}

// ---------------- tag projection: feats = [hf|hb] @ Wtag^T + btag ----------------
__global__ void __launch_bounds__(256) feats_kernel(const float* __restrict__ Wtag,
                                                    const float* __restrict__ btag) {
    __shared__ float Wt_s[6144];
    __shared__ float bt_s[12];
    int tid = threadIdx.x;
    for (int i = tid; i < 1536; i += 256)
        ((float4*)Wt_s)[i] = ((const float4*)Wtag)[i];
    if (tid < 12) bt_s[tid] = btag[tid];
    __syncthreads();

    int b = blockIdx.y, tg = blockIdx.x;
    int w = tid >> 5, lane = tid & 31;
    int t = tg * 8 + w;
    const float* hrow = g_hall + ((size_t)(b * 1024 + t)) * 512;
    float4 hv[4];
#pragma unroll
    for (int r = 0; r < 4; r++) hv[r] = *(const float4*)(hrow + r * 128 + lane * 4);
    float* fo = g_feats + (b * 1024 + t) * 12;
#pragma unroll
    for (int k = 0; k < 12; k++) {
        float s = 0.f;
#pragma unroll
        for (int r = 0; r < 4; r++) {
            float4 wv = *(const float4*)&Wt_s[k * 512 + r * 128 + lane * 4];
            s += hv[r].x * wv.x + hv[r].y * wv.y + hv[r].z * wv.z + hv[r].w * wv.w;
        }
#pragma unroll
        for (int o = 16; o > 0; o >>= 1) s += __shfl_down_sync(0xffffffffu, s, o);
        if (lane == 0) fo[k] = s + bt_s[k];
    }
}

// ---------------- Viterbi + backtrace (one block per batch element) ----------------
__global__ void viterbi_kernel(const float* __restrict__ transitions,
                               const int*   __restrict__ seq_lens,
                               float* __restrict__ out) {
    extern __shared__ float vsm[];
    float* feats_s = vsm;                                   // 12288 floats
    float* fv      = vsm + 12288;                           // 16 floats
    unsigned char* bp = (unsigned char*)(vsm + 12304);      // 12288 bytes

    int b = blockIdx.x, tid = threadIdx.x;
    const float4* fsrc = (const float4*)(g_feats + (size_t)b * 12288);
    for (int i = tid; i < 3072; i += blockDim.x) ((float4*)feats_s)[i] = fsrc[i];
    int len = seq_lens[b];
    if (tid < 12) fv[tid] = (tid == 10) ? 0.f : NEGV;   // START = 10
    __syncthreads();

    if (tid < 32) {
        float tr[12];
        if (tid < 12) {
#pragma unroll
            for (int j = 0; j < 12; j++) tr[j] = transitions[tid * 12 + j];
        }
        for (int t = 0; t < 1024; t++) {
            float best = 0.f, nf = 0.f; int bj = 0;
            if (tid < 12) {
                best = fv[0] + tr[0]; bj = 0;
#pragma unroll
                for (int j = 1; j < 12; j++) {
                    float s = fv[j] + tr[j];
                    if (s > best) { best = s; bj = j; }   // first-max tie-break
                }
                nf = best + feats_s[t * 12 + tid];
            }
            bool m = (t < len);
            __syncwarp();
            if (tid < 12) {
                bp[t * 12 + tid] = (unsigned char)(m ? bj : tid);
                if (m) fv[tid] = nf;
            }
            __syncwarp();
        }
        if (tid == 0) {
            float bestv = -3.4e38f; int bt = 0;
            for (int k = 0; k < 12; k++) {
                float tv = fv[k] + transitions[11 * 12 + k];   // STOP = 11
                if (tv > bestv) { bestv = tv; bt = k; }
            }
            out[b] = bestv;
            float* po = out + 64 + (size_t)b * 1024;
            int tag = bt;
            for (int t = 1023; t >= 0; t--) {
                po[t] = (t < len) ? (float)tag : 0.f;
                tag = bp[t * 12 + tag];
            }
        }
    }
}

extern "C" void kernel_launch(void* const* d_in, const int* in_sizes, int n_in,
                              void* d_out, int out_size) {
    const int*   sent     = (const int*)  d_in[0];
    const int*   seq_lens = (const int*)  d_in[1];
    const float* emb      = (const float*)d_in[2];
    const float* Wih_f    = (const float*)d_in[3];
    const float* Whh_f    = (const float*)d_in[4];
    const float* bih_f    = (const float*)d_in[5];
    const float* bhh_f    = (const float*)d_in[6];
    const float* Wih_b    = (const float*)d_in[7];
    const float* Whh_b    = (const float*)d_in[8];
    const float* bih_b    = (const float*)d_in[9];
    const float* bhh_b    = (const float*)d_in[10];
    const float* Wtag     = (const float*)d_in[11];
    const float* btag     = (const float*)d_in[12];
    const float* trans    = (const float*)d_in[13];
    const float* h0       = (const float*)d_in[14];
    const float* c0       = (const float*)d_in[15];
    float* out = (float*)d_out;
    (void)in_sizes; (void)n_in; (void)out_size;

    cudaFuncSetAttribute(viterbi_kernel,
                         cudaFuncAttributeMaxDynamicSharedMemorySize, 61504);

    prep_kernel<<<512, 256>>>(Wih_f, Wih_b, bih_f, bhh_f, bih_b, bhh_b, h0);
    gemm_kernel<<<dim3(16, 512), 256>>>(sent, emb);
    lstm_kernel<<<128, 256>>>(Whh_f, Whh_b, c0, seq_lens);
    feats_kernel<<<dim3(128, 64), 256>>>(Wtag, btag);
    viterbi_kernel<<<64, 128, 61504>>>(trans, seq_lens, out);
}

// round 11
// speedup vs baseline: 1.9945x; 1.9945x over previous
#include <cuda_runtime.h>
#include <math.h>
#include <stdint.h>

// Problem constants: B=64, T=1024, V=50000, D=256, Hh=256, H=512, K=12
#define NEGV (-10000.0f)

// ---------------- device scratch (no cudaMalloc allowed) ----------------
__device__ float    g_xz[134217728];   // [1024 t][2048 n][64 b]  gate preacts
__device__ float    g_hall[33554432];  // [64 b][1024 t][512]     all hidden states
__device__ float    g_hbuf[2][32768];  // ping-pong h [parity][dir*16384 + b*256 + u]
__device__ float    g_Wt[524288];      // [256 k][2048 n]  transposed input weights
__device__ float    g_bias[2048];      // bih+bhh, forward | backward
__device__ float    g_feats[786432];   // [64 b][1024 t][12 k]
__device__ unsigned g_ctr[2];          // per-direction grid-barrier counters (R8 barrier)

// precise activations (fast-math variants flipped Viterbi argmax ties in R7)
__device__ __forceinline__ float sig_p(float x)  { return 1.f / (1.f + expf(-x)); }

// packed f32x2 helpers (pairs two IEEE-exact fp32 FMAs per instruction)
__device__ __forceinline__ unsigned long long pk2(float lo, float hi) {
    unsigned long long r;
    asm("mov.b64 %0, {%1, %2};" : "=l"(r) : "f"(lo), "f"(hi));
    return r;
}
__device__ __forceinline__ void fma2(unsigned long long& acc,
                                     unsigned long long a, unsigned long long b) {
    asm("fma.rn.f32x2 %0, %1, %2, %0;" : "+l"(acc) : "l"(a), "l"(b));
}
__device__ __forceinline__ float hsum2(unsigned long long s0, unsigned long long s1) {
    unsigned long long s;
    asm("add.rn.f32x2 %0, %1, %2;" : "=l"(s) : "l"(s0), "l"(s1));
    float lo, hi;
    asm("mov.b64 {%0, %1}, %2;" : "=f"(lo), "=f"(hi) : "l"(s));
    return lo + hi;
}
__device__ __forceinline__ void upk2(unsigned long long v, float& lo, float& hi) {
    asm("mov.b64 {%0, %1}, %2;" : "=f"(lo), "=f"(hi) : "l"(v));
}

// ---------------- prep: transpose Wih, fold biases, init h buffer ----------------
__global__ void prep_kernel(const float* __restrict__ Wih_f, const float* __restrict__ Wih_b,
                            const float* __restrict__ bih_f, const float* __restrict__ bhh_f,
                            const float* __restrict__ bih_b, const float* __restrict__ bhh_b,
                            const float* __restrict__ h0) {
    int i  = blockIdx.x * blockDim.x + threadIdx.x;
    int nt = gridDim.x * blockDim.x;
    for (int e = i; e < 524288; e += nt) {
        int k = e >> 11, n = e & 2047;
        g_Wt[e] = (n < 1024) ? Wih_f[n * 256 + k] : Wih_b[(n - 1024) * 256 + k];
    }
    if (i < 2048) g_bias[i] = (i < 1024) ? (bih_f[i] + bhh_f[i])
                                         : (bih_b[i - 1024] + bhh_b[i - 1024]);
    if (i < 32768) g_hbuf[0][i] = h0[i];   // h0 is [2][64][256] flat
    if (i < 2) g_ctr[i] = 0u;
}

// ---------------- gather-SGEMM: xz = emb[sent] @ Wt + bias (FFMA2, R9 version) --------
// m is t-major: m = t*64 + b (epilogue stores to [t][n][b] coalesced in b).
// 128x128x8 tile, 256 thr, 8x8 microtile; FFMA2-paired along j (k-order of each
// accumulator is bit-identical to the scalar version).
__global__ void __launch_bounds__(256) gemm_kernel(const int* __restrict__ sent,
                                                   const float* __restrict__ emb) {
    __shared__ float As[8][128];
    __shared__ float Bs[8][128];
    __shared__ int   idx[128];
    int tid = threadIdx.x;
    int m0 = blockIdx.y * 128;
    int n0 = blockIdx.x * 128;
    if (tid < 128) {
        int m = m0 + tid;                       // m = t*64 + b
        idx[tid] = sent[(m & 63) * 1024 + (m >> 6)];
    }
    __syncthreads();

    unsigned long long acc2[8][4];
#pragma unroll
    for (int i = 0; i < 8; i++)
#pragma unroll
        for (int j = 0; j < 4; j++) acc2[i][j] = 0ULL;

    int rbase = tid & 15, nty = tid >> 4;      // rows: rbase+16i ; cols: nty*8+j
    int ar = tid >> 1, akq = (tid & 1) * 4;    // A-tile load coords
    int bkr = tid >> 5, bnc = (tid & 31) * 4;  // B-tile load coords
    const float* arow = emb + (size_t)idx[ar] * 256;

    for (int kt = 0; kt < 256; kt += 8) {
        float4 av = *(const float4*)(arow + kt + akq);
        As[akq + 0][ar] = av.x; As[akq + 1][ar] = av.y;
        As[akq + 2][ar] = av.z; As[akq + 3][ar] = av.w;
        *(float4*)&Bs[bkr][bnc] =
            *(const float4*)&g_Wt[(size_t)(kt + bkr) * 2048 + n0 + bnc];
        __syncthreads();
#pragma unroll
        for (int k = 0; k < 8; k++) {
            unsigned long long a2[8], b2[4];
#pragma unroll
            for (int i = 0; i < 8; i++) {
                float a = As[k][rbase + 16 * i];
                a2[i] = pk2(a, a);
            }
            float4 b0 = *(float4*)&Bs[k][nty * 8];
            float4 b1 = *(float4*)&Bs[k][nty * 8 + 4];
            b2[0] = pk2(b0.x, b0.y); b2[1] = pk2(b0.z, b0.w);
            b2[2] = pk2(b1.x, b1.y); b2[3] = pk2(b1.z, b1.w);
#pragma unroll
            for (int i = 0; i < 8; i++)
#pragma unroll
                for (int j = 0; j < 4; j++) fma2(acc2[i][j], a2[i], b2[j]);
        }
        __syncthreads();
    }

#pragma unroll
    for (int i = 0; i < 8; i++) {
        int mm = m0 + rbase + 16 * i;
        int tt = mm >> 6, b = mm & 63;
        float* orow = g_xz + (size_t)tt * 131072 + b;   // [t][n][b]
#pragma unroll
        for (int j = 0; j < 4; j++) {
            int n = n0 + nty * 8 + 2 * j;
            float lo, hi; upk2(acc2[i][j], lo, hi);
            orow[(size_t)n * 64]       = lo + g_bias[n];
            orow[(size_t)(n + 1) * 64] = hi + g_bias[n + 1];
        }
    }
}

// ---------------- persistent BiLSTM recurrence (W-stationary, FFMA2, R8 barrier) ------
// 128 blocks: dir = bx>>6, ublk = bx&63 (4 hidden units -> 16 gate rows).
// 256 threads = 8 warps; warp w owns batch b = w*8 .. w*8+7.
// kc = lane&15 (k-partition: {q*64 + kc*4 + 0..3}), half = lane>>4 (8 rows).
// W slice in registers as f32x2 pairs; butterfly reduction over k lane bits.
// Barrier: R8's threadfence + single-counter atomicAdd + tid0 volatile spin.
__global__ void __launch_bounds__(256, 1) lstm_kernel(const float* __restrict__ Whh_f,
                                                      const float* __restrict__ Whh_b,
                                                      const float* __restrict__ c0,
                                                      const int*   __restrict__ seq_lens) {
    __shared__ float z_s[1024];   // [warp][bb][row] = [8][8][16]

    int tid  = threadIdx.x;
    int w    = tid >> 5;
    int lane = tid & 31;
    int dir  = blockIdx.x >> 6;
    int ublk = blockIdx.x & 63;
    int kc   = lane & 15;
    int half = lane >> 4;
    int l3 = (lane >> 3) & 1, l2 = (lane >> 2) & 1, l1 = (lane >> 1) & 1;

    const float* Whh = dir ? Whh_b : Whh_f;

    // W slice as f32x2 pairs: Wv2[rr][q] covers k = q*64 + kc*4 .. +3
    ulonglong2 Wv2[8][4];
#pragma unroll
    for (int rr = 0; rr < 8; rr++) {
        int rl = half * 8 + rr;
        int g = rl >> 2, u = rl & 3;
        const float* wrow = Whh + ((size_t)(g * 256 + ublk * 4 + u)) * 256;
#pragma unroll
        for (int q = 0; q < 4; q++)
            Wv2[rr][q] = __ldg((const ulonglong2*)(wrow + q * 64 + kc * 4));
    }

    // Elementwise-phase identity: lane -> (bb, u) cell
    int bb_e = lane >> 2, u_e = lane & 3;
    int b_e  = w * 8 + bb_e;
    int ug_e = ublk * 4 + u_e;
    float c     = __ldg(&c0[dir * 16384 + b_e * 256 + ug_e]);
    float hprev = g_hbuf[0][dir * 16384 + b_e * 256 + ug_e];
    int   len   = __ldg(&seq_lens[b_e]);
    unsigned* ctr = &g_ctr[dir];
    int  zrow   = half * 8 + ((lane >> 1) & 7);
    bool do_sts = ((lane & 1) == 0);
    float* zw   = z_s + w * 128 + bb_e * 16;

    for (int step = 0; step < 1024; step++) {
        int p = step & 1;
        int t = dir ? (1023 - step) : step;
        const float* hsrc = g_hbuf[p] + dir * 16384;

        // prefetch b = w*8
        ulonglong2 hv[4], hn4[4];
        {
            const float* hb0 = hsrc + (w * 8) * 256;
#pragma unroll
            for (int q = 0; q < 4; q++)
                hv[q] = __ldcg((const ulonglong2*)(hb0 + q * 64 + kc * 4));
        }
#pragma unroll
        for (int bb = 0; bb < 8; bb++) {
            if (bb < 7) {
                const float* hbn = hsrc + (w * 8 + bb + 1) * 256;
#pragma unroll
                for (int q = 0; q < 4; q++)
                    hn4[q] = __ldcg((const ulonglong2*)(hbn + q * 64 + kc * 4));
            }
            float acc[8];
#pragma unroll
            for (int rr = 0; rr < 8; rr++) {
                unsigned long long s0 = 0ULL, s1 = 0ULL;
#pragma unroll
                for (int q = 0; q < 4; q++) {
                    fma2(s0, Wv2[rr][q].x, hv[q].x);
                    fma2(s1, Wv2[rr][q].y, hv[q].y);
                }
                acc[rr] = hsum2(s0, s1);
            }
            // register-halving butterfly reduction over k (lane bits 3..0)
#pragma unroll
            for (int j = 0; j < 4; j++) {
                float send = l3 ? acc[j] : acc[j + 4];
                float recv = __shfl_xor_sync(0xffffffffu, send, 8);
                acc[j] = (l3 ? acc[j + 4] : acc[j]) + recv;
            }
#pragma unroll
            for (int j = 0; j < 2; j++) {
                float send = l2 ? acc[j] : acc[j + 2];
                float recv = __shfl_xor_sync(0xffffffffu, send, 4);
                acc[j] = (l2 ? acc[j + 2] : acc[j]) + recv;
            }
            {
                float send = l1 ? acc[0] : acc[1];
                float recv = __shfl_xor_sync(0xffffffffu, send, 2);
                acc[0] = (l1 ? acc[1] : acc[0]) + recv;
            }
            acc[0] += __shfl_xor_sync(0xffffffffu, acc[0], 1);
            if (do_sts) z_s[w * 128 + bb * 16 + zrow] = acc[0];
#pragma unroll
            for (int q = 0; q < 4; q++) hv[q] = hn4[q];
        }
        __syncwarp();

        // elementwise: lane owns cell (b_e, u_e) — precise activations
        float zi = zw[0 + u_e], zf = zw[4 + u_e], zg = zw[8 + u_e], zo = zw[12 + u_e];
        const float* xzp = g_xz + ((size_t)t * 2048 + dir * 1024 + ug_e) * 64 + b_e;
        zi += __ldg(xzp);
        zf += __ldg(xzp + 16384);
        zg += __ldg(xzp + 32768);
        zo += __ldg(xzp + 49152);

        float ai = sig_p(zi), af = sig_p(zf), ag = tanhf(zg), ao = sig_p(zo);
        float c2 = af * c + ai * ag;
        float h2 = ao * tanhf(c2);

        bool m = (t < len);
        if (m) c = c2;
        float hn = m ? h2 : hprev;
        hprev = hn;

        g_hbuf[p ^ 1][dir * 16384 + b_e * 256 + ug_e] = hn;
        g_hall[((size_t)(b_e * 1024 + t)) * 512 + dir * 256 + ug_e] = hn;

        // R8 grid barrier: threadfence + single-counter atomicAdd + tid0 spin
        __threadfence();
        __syncthreads();
        if (tid == 0) {
            atomicAdd(ctr, 1u);
            unsigned target = 64u * (unsigned)(step + 1);
            while (*((volatile unsigned*)ctr) < target) { }
        }
        __syncthreads();
    }
}

// ---------------- tag projection: feats = [hf|hb] @ Wtag^T + btag ----------------
__global__ void __launch_bounds__(256) feats_kernel(const float* __restrict__ Wtag,
                                                    const float* __restrict__ btag) {
    __shared__ float Wt_s[6144];
    __shared__ float bt_s[12];
    int tid = threadIdx.x;
    for (int i = tid; i < 1536; i += 256)
        ((float4*)Wt_s)[i] = ((const float4*)Wtag)[i];
    if (tid < 12) bt_s[tid] = btag[tid];
    __syncthreads();

    int b = blockIdx.y, tg = blockIdx.x;
    int w = tid >> 5, lane = tid & 31;
    int t = tg * 8 + w;
    const float* hrow = g_hall + ((size_t)(b * 1024 + t)) * 512;
    float4 hv[4];
#pragma unroll
    for (int r = 0; r < 4; r++) hv[r] = *(const float4*)(hrow + r * 128 + lane * 4);
    float* fo = g_feats + (b * 1024 + t) * 12;
#pragma unroll
    for (int k = 0; k < 12; k++) {
        float s = 0.f;
#pragma unroll
        for (int r = 0; r < 4; r++) {
            float4 wv = *(const float4*)&Wt_s[k * 512 + r * 128 + lane * 4];
            s += hv[r].x * wv.x + hv[r].y * wv.y + hv[r].z * wv.z + hv[r].w * wv.w;
        }
#pragma unroll
        for (int o = 16; o > 0; o >>= 1) s += __shfl_down_sync(0xffffffffu, s, o);
        if (lane == 0) fo[k] = s + bt_s[k];
    }
}

// ---------------- Viterbi + backtrace (one block per batch element) ----------------
__global__ void viterbi_kernel(const float* __restrict__ transitions,
                               const int*   __restrict__ seq_lens,
                               float* __restrict__ out) {
    extern __shared__ float vsm[];
    float* feats_s = vsm;                                   // 12288 floats
    float* fv      = vsm + 12288;                           // 16 floats
    unsigned char* bp = (unsigned char*)(vsm + 12304);      // 12288 bytes

    int b = blockIdx.x, tid = threadIdx.x;
    const float4* fsrc = (const float4*)(g_feats + (size_t)b * 12288);
    for (int i = tid; i < 3072; i += blockDim.x) ((float4*)feats_s)[i] = fsrc[i];
    int len = seq_lens[b];
    if (tid < 12) fv[tid] = (tid == 10) ? 0.f : NEGV;   // START = 10
    __syncthreads();

    if (tid < 32) {
        float tr[12];
        if (tid < 12) {
#pragma unroll
            for (int j = 0; j < 12; j++) tr[j] = transitions[tid * 12 + j];
        }
        for (int t = 0; t < 1024; t++) {
            float best = 0.f, nf = 0.f; int bj = 0;
            if (tid < 12) {
                best = fv[0] + tr[0]; bj = 0;
#pragma unroll
                for (int j = 1; j < 12; j++) {
                    float s = fv[j] + tr[j];
                    if (s > best) { best = s; bj = j; }   // first-max tie-break
                }
                nf = best + feats_s[t * 12 + tid];
            }
            bool m = (t < len);
            __syncwarp();
            if (tid < 12) {
                bp[t * 12 + tid] = (unsigned char)(m ? bj : tid);
                if (m) fv[tid] = nf;
            }
            __syncwarp();
        }
        if (tid == 0) {
            float bestv = -3.4e38f; int bt = 0;
            for (int k = 0; k < 12; k++) {
                float tv = fv[k] + transitions[11 * 12 + k];   // STOP = 11
                if (tv > bestv) { bestv = tv; bt = k; }
            }
            out[b] = bestv;
            float* po = out + 64 + (size_t)b * 1024;
            int tag = bt;
            for (int t = 1023; t >= 0; t--) {
                po[t] = (t < len) ? (float)tag : 0.f;
                tag = bp[t * 12 + tag];
            }
        }
    }
}

extern "C" void kernel_launch(void* const* d_in, const int* in_sizes, int n_in,
                              void* d_out, int out_size) {
    const int*   sent     = (const int*)  d_in[0];
    const int*   seq_lens = (const int*)  d_in[1];
    const float* emb      = (const float*)d_in[2];
    const float* Wih_f    = (const float*)d_in[3];
    const float* Whh_f    = (const float*)d_in[4];
    const float* bih_f    = (const float*)d_in[5];
    const float* bhh_f    = (const float*)d_in[6];
    const float* Wih_b    = (const float*)d_in[7];
    const float* Whh_b    = (const float*)d_in[8];
    const float* bih_b    = (const float*)d_in[9];
    const float* bhh_b    = (const float*)d_in[10];
    const float* Wtag     = (const float*)d_in[11];
    const float* btag     = (const float*)d_in[12];
    const float* trans    = (const float*)d_in[13];
    const float* h0       = (const float*)d_in[14];
    const float* c0       = (const float*)d_in[15];
    float* out = (float*)d_out;
    (void)in_sizes; (void)n_in; (void)out_size;

    cudaFuncSetAttribute(viterbi_kernel,
                         cudaFuncAttributeMaxDynamicSharedMemorySize, 61504);

    prep_kernel<<<512, 256>>>(Wih_f, Wih_b, bih_f, bhh_f, bih_b, bhh_b, h0);
    gemm_kernel<<<dim3(16, 512), 256>>>(sent, emb);
    lstm_kernel<<<128, 256>>>(Whh_f, Whh_b, c0, seq_lens);
    feats_kernel<<<dim3(128, 64), 256>>>(Wtag, btag);
    viterbi_kernel<<<64, 128, 61504>>>(trans, seq_lens, out);
}

// round 12
// speedup vs baseline: 2.0192x; 1.0124x over previous
#include <cuda_runtime.h>
#include <math.h>
#include <stdint.h>

// Problem constants: B=64, T=1024, V=50000, D=256, Hh=256, H=512, K=12
#define NEGV (-10000.0f)

// ---------------- device scratch (no cudaMalloc allowed) ----------------
__device__ float    g_xz[134217728];   // [1024 t][2048 n][64 b]  gate preacts
__device__ float    g_hall[33554432];  // [64 b][1024 t][512]     all hidden states
__device__ float    g_hbuf[2][32768];  // ping-pong h [parity][dir*16384 + b*256 + u]
__device__ float    g_Wt[524288];      // [256 k][2048 n]  transposed input weights
__device__ float    g_bias[2048];      // bih+bhh, forward | backward
__device__ float    g_feats[786432];   // [64 b][1024 t][12 k]
__device__ unsigned g_ctr[2];          // per-direction grid-barrier counters (R8 barrier)

// precise activations (fast-math variants flipped Viterbi argmax ties in R7)
__device__ __forceinline__ float sig_p(float x)  { return 1.f / (1.f + expf(-x)); }

// packed f32x2 helpers (pairs two IEEE-exact fp32 FMAs per instruction)
__device__ __forceinline__ unsigned long long pk2(float lo, float hi) {
    unsigned long long r;
    asm("mov.b64 %0, {%1, %2};" : "=l"(r) : "f"(lo), "f"(hi));
    return r;
}
__device__ __forceinline__ void fma2(unsigned long long& acc,
                                     unsigned long long a, unsigned long long b) {
    asm("fma.rn.f32x2 %0, %1, %2, %0;" : "+l"(acc) : "l"(a), "l"(b));
}
__device__ __forceinline__ void upk2(unsigned long long v, float& lo, float& hi) {
    asm("mov.b64 {%0, %1}, %2;" : "=f"(lo), "=f"(hi) : "l"(v));
}

// ---------------- prep: transpose Wih, fold biases, init h buffer ----------------
__global__ void prep_kernel(const float* __restrict__ Wih_f, const float* __restrict__ Wih_b,
                            const float* __restrict__ bih_f, const float* __restrict__ bhh_f,
                            const float* __restrict__ bih_b, const float* __restrict__ bhh_b,
                            const float* __restrict__ h0) {
    int i  = blockIdx.x * blockDim.x + threadIdx.x;
    int nt = gridDim.x * blockDim.x;
    for (int e = i; e < 524288; e += nt) {
        int k = e >> 11, n = e & 2047;
        g_Wt[e] = (n < 1024) ? Wih_f[n * 256 + k] : Wih_b[(n - 1024) * 256 + k];
    }
    if (i < 2048) g_bias[i] = (i < 1024) ? (bih_f[i] + bhh_f[i])
                                         : (bih_b[i - 1024] + bhh_b[i - 1024]);
    if (i < 32768) g_hbuf[0][i] = h0[i];   // h0 is [2][64][256] flat
    if (i < 2) g_ctr[i] = 0u;
}

// ---------------- gather-SGEMM: xz = emb[sent] @ Wt + bias (FFMA2, R11-exact) ---------
__global__ void __launch_bounds__(256) gemm_kernel(const int* __restrict__ sent,
                                                   const float* __restrict__ emb) {
    __shared__ float As[8][128];
    __shared__ float Bs[8][128];
    __shared__ int   idx[128];
    int tid = threadIdx.x;
    int m0 = blockIdx.y * 128;
    int n0 = blockIdx.x * 128;
    if (tid < 128) {
        int m = m0 + tid;                       // m = t*64 + b
        idx[tid] = sent[(m & 63) * 1024 + (m >> 6)];
    }
    __syncthreads();

    unsigned long long acc2[8][4];
#pragma unroll
    for (int i = 0; i < 8; i++)
#pragma unroll
        for (int j = 0; j < 4; j++) acc2[i][j] = 0ULL;

    int rbase = tid & 15, nty = tid >> 4;      // rows: rbase+16i ; cols: nty*8+j
    int ar = tid >> 1, akq = (tid & 1) * 4;    // A-tile load coords
    int bkr = tid >> 5, bnc = (tid & 31) * 4;  // B-tile load coords
    const float* arow = emb + (size_t)idx[ar] * 256;

    for (int kt = 0; kt < 256; kt += 8) {
        float4 av = *(const float4*)(arow + kt + akq);
        As[akq + 0][ar] = av.x; As[akq + 1][ar] = av.y;
        As[akq + 2][ar] = av.z; As[akq + 3][ar] = av.w;
        *(float4*)&Bs[bkr][bnc] =
            *(const float4*)&g_Wt[(size_t)(kt + bkr) * 2048 + n0 + bnc];
        __syncthreads();
#pragma unroll
        for (int k = 0; k < 8; k++) {
            unsigned long long a2[8], b2[4];
#pragma unroll
            for (int i = 0; i < 8; i++) {
                float a = As[k][rbase + 16 * i];
                a2[i] = pk2(a, a);
            }
            float4 b0 = *(float4*)&Bs[k][nty * 8];
            float4 b1 = *(float4*)&Bs[k][nty * 8 + 4];
            b2[0] = pk2(b0.x, b0.y); b2[1] = pk2(b0.z, b0.w);
            b2[2] = pk2(b1.x, b1.y); b2[3] = pk2(b1.z, b1.w);
#pragma unroll
            for (int i = 0; i < 8; i++)
#pragma unroll
                for (int j = 0; j < 4; j++) fma2(acc2[i][j], a2[i], b2[j]);
        }
        __syncthreads();
    }

#pragma unroll
    for (int i = 0; i < 8; i++) {
        int mm = m0 + rbase + 16 * i;
        int tt = mm >> 6, b = mm & 63;
        float* orow = g_xz + (size_t)tt * 131072 + b;   // [t][n][b]
#pragma unroll
        for (int j = 0; j < 4; j++) {
            int n = n0 + nty * 8 + 2 * j;
            float lo, hi; upk2(acc2[i][j], lo, hi);
            orow[(size_t)n * 64]       = lo + g_bias[n];
            orow[(size_t)(n + 1) * 64] = hi + g_bias[n + 1];
        }
    }
}

// ---------------- persistent BiLSTM recurrence ----------------
// 128 blocks: dir = bx>>6, ublk = bx&63 (4 hidden units -> 16 gate rows).
// 256 threads = 8 warps; warp w owns batch b = w*8 .. w*8+7.
// NEW layout (no duplicate k-loads): lane owns k in {lane*4..+3} U {128+lane*4..+3}
// -> per (warp,b) exactly two fully-coalesced 512B LDG.128 sweeps (h read once).
// Each lane computes ALL 16 gate rows over its 8 k's (W regs 16x8 = 128 floats).
// Reduction: 5-round register-halving butterfly; final row = lane>>1 (even lanes store).
// g_xz[t] prefetched at step top to hide DRAM latency under the bb loop.
// Barrier: R8's threadfence + single-counter atomicAdd + tid0 volatile spin.
__global__ void __launch_bounds__(256, 1) lstm_kernel(const float* __restrict__ Whh_f,
                                                      const float* __restrict__ Whh_b,
                                                      const float* __restrict__ c0,
                                                      const int*   __restrict__ seq_lens) {
    __shared__ float z_s[1024];   // [warp][bb][row] = [8][8][16]

    int tid  = threadIdx.x;
    int w    = tid >> 5;
    int lane = tid & 31;
    int dir  = blockIdx.x >> 6;
    int ublk = blockIdx.x & 63;
    int l4 = (lane >> 4) & 1, l3 = (lane >> 3) & 1, l2 = (lane >> 2) & 1, l1 = (lane >> 1) & 1;

    const float* Whh = dir ? Whh_b : Whh_f;

    // W slice: Wv2[rr][0] covers k = lane*4..+3, Wv2[rr][1] covers k = 128+lane*4..+3
    ulonglong2 Wv2[16][2];
#pragma unroll
    for (int rr = 0; rr < 16; rr++) {
        int g = rr >> 2, u = rr & 3;
        const float* wrow = Whh + ((size_t)(g * 256 + ublk * 4 + u)) * 256;
        Wv2[rr][0] = __ldg((const ulonglong2*)(wrow + lane * 4));
        Wv2[rr][1] = __ldg((const ulonglong2*)(wrow + 128 + lane * 4));
    }

    // Elementwise-phase identity: lane -> (bb, u) cell
    int bb_e = lane >> 2, u_e = lane & 3;
    int b_e  = w * 8 + bb_e;
    int ug_e = ublk * 4 + u_e;
    float c     = __ldg(&c0[dir * 16384 + b_e * 256 + ug_e]);
    float hprev = g_hbuf[0][dir * 16384 + b_e * 256 + ug_e];
    int   len   = __ldg(&seq_lens[b_e]);
    unsigned* ctr = &g_ctr[dir];
    int  zrow   = lane >> 1;
    bool do_sts = ((lane & 1) == 0);
    float* zw   = z_s + w * 128 + bb_e * 16;

    for (int step = 0; step < 1024; step++) {
        int p = step & 1;
        int t = dir ? (1023 - step) : step;
        const float* hsrc = g_hbuf[p] + dir * 16384;

        // prefetch this step's xz gate preacts (independent of h -> hides DRAM lat)
        const float* xzp = g_xz + ((size_t)t * 2048 + dir * 1024 + ug_e) * 64 + b_e;
        float xi = __ldg(xzp);
        float xf = __ldg(xzp + 16384);
        float xg = __ldg(xzp + 32768);
        float xo = __ldg(xzp + 49152);

        // prefetch h for b = w*8
        ulonglong2 hv0, hv1, hn0, hn1;
        {
            const float* hb = hsrc + (w * 8) * 256;
            hv0 = __ldcg((const ulonglong2*)(hb + lane * 4));
            hv1 = __ldcg((const ulonglong2*)(hb + 128 + lane * 4));
        }
#pragma unroll
        for (int bb = 0; bb < 8; bb++) {
            if (bb < 7) {
                const float* hb = hsrc + (w * 8 + bb + 1) * 256;
                hn0 = __ldcg((const ulonglong2*)(hb + lane * 4));
                hn1 = __ldcg((const ulonglong2*)(hb + 128 + lane * 4));
            }
            float acc[16];
#pragma unroll
            for (int rr = 0; rr < 16; rr++) {
                unsigned long long s = 0ULL;
                fma2(s, Wv2[rr][0].x, hv0.x);
                fma2(s, Wv2[rr][0].y, hv0.y);
                fma2(s, Wv2[rr][1].x, hv1.x);
                fma2(s, Wv2[rr][1].y, hv1.y);
                float lo, hi; upk2(s, lo, hi);
                acc[rr] = lo + hi;
            }
            // register-halving butterfly over lane bits 4..1, then allreduce bit 0
#pragma unroll
            for (int j = 0; j < 8; j++) {
                float send = l4 ? acc[j] : acc[j + 8];
                float recv = __shfl_xor_sync(0xffffffffu, send, 16);
                acc[j] = (l4 ? acc[j + 8] : acc[j]) + recv;
            }
#pragma unroll
            for (int j = 0; j < 4; j++) {
                float send = l3 ? acc[j] : acc[j + 4];
                float recv = __shfl_xor_sync(0xffffffffu, send, 8);
                acc[j] = (l3 ? acc[j + 4] : acc[j]) + recv;
            }
#pragma unroll
            for (int j = 0; j < 2; j++) {
                float send = l2 ? acc[j] : acc[j + 2];
                float recv = __shfl_xor_sync(0xffffffffu, send, 4);
                acc[j] = (l2 ? acc[j + 2] : acc[j]) + recv;
            }
            {
                float send = l1 ? acc[0] : acc[1];
                float recv = __shfl_xor_sync(0xffffffffu, send, 2);
                acc[0] = (l1 ? acc[1] : acc[0]) + recv;
            }
            acc[0] += __shfl_xor_sync(0xffffffffu, acc[0], 1);
            if (do_sts) z_s[w * 128 + bb * 16 + zrow] = acc[0];
            hv0 = hn0; hv1 = hn1;
        }
        __syncwarp();

        // elementwise: lane owns cell (b_e, u_e) — precise activations
        float zi = zw[0 + u_e] + xi;
        float zf = zw[4 + u_e] + xf;
        float zg = zw[8 + u_e] + xg;
        float zo = zw[12 + u_e] + xo;

        float ai = sig_p(zi), af = sig_p(zf), ag = tanhf(zg), ao = sig_p(zo);
        float c2 = af * c + ai * ag;
        float h2 = ao * tanhf(c2);

        bool m = (t < len);
        if (m) c = c2;
        float hn = m ? h2 : hprev;
        hprev = hn;

        g_hbuf[p ^ 1][dir * 16384 + b_e * 256 + ug_e] = hn;
        g_hall[((size_t)(b_e * 1024 + t)) * 512 + dir * 256 + ug_e] = hn;

        // R8 grid barrier: threadfence + single-counter atomicAdd + tid0 spin
        __threadfence();
        __syncthreads();
        if (tid == 0) {
            atomicAdd(ctr, 1u);
            unsigned target = 64u * (unsigned)(step + 1);
            while (*((volatile unsigned*)ctr) < target) { }
        }
        __syncthreads();
    }
}

// ---------------- tag projection: feats = [hf|hb] @ Wtag^T + btag ----------------
__global__ void __launch_bounds__(256) feats_kernel(const float* __restrict__ Wtag,
                                                    const float* __restrict__ btag) {
    __shared__ float Wt_s[6144];
    __shared__ float bt_s[12];
    int tid = threadIdx.x;
    for (int i = tid; i < 1536; i += 256)
        ((float4*)Wt_s)[i] = ((const float4*)Wtag)[i];
    if (tid < 12) bt_s[tid] = btag[tid];
    __syncthreads();

    int b = blockIdx.y, tg = blockIdx.x;
    int w = tid >> 5, lane = tid & 31;
    int t = tg * 8 + w;
    const float* hrow = g_hall + ((size_t)(b * 1024 + t)) * 512;
    float4 hv[4];
#pragma unroll
    for (int r = 0; r < 4; r++) hv[r] = *(const float4*)(hrow + r * 128 + lane * 4);
    float* fo = g_feats + (b * 1024 + t) * 12;
#pragma unroll
    for (int k = 0; k < 12; k++) {
        float s = 0.f;
#pragma unroll
        for (int r = 0; r < 4; r++) {
            float4 wv = *(const float4*)&Wt_s[k * 512 + r * 128 + lane * 4];
            s += hv[r].x * wv.x + hv[r].y * wv.y + hv[r].z * wv.z + hv[r].w * wv.w;
        }
#pragma unroll
        for (int o = 16; o > 0; o >>= 1) s += __shfl_down_sync(0xffffffffu, s, o);
        if (lane == 0) fo[k] = s + bt_s[k];
    }
}

// ---------------- Viterbi + backtrace (one block per batch element) ----------------
__global__ void viterbi_kernel(const float* __restrict__ transitions,
                               const int*   __restrict__ seq_lens,
                               float* __restrict__ out) {
    extern __shared__ float vsm[];
    float* feats_s = vsm;                                   // 12288 floats
    float* fv      = vsm + 12288;                           // 16 floats
    unsigned char* bp = (unsigned char*)(vsm + 12304);      // 12288 bytes

    int b = blockIdx.x, tid = threadIdx.x;
    const float4* fsrc = (const float4*)(g_feats + (size_t)b * 12288);
    for (int i = tid; i < 3072; i += blockDim.x) ((float4*)feats_s)[i] = fsrc[i];
    int len = seq_lens[b];
    if (tid < 12) fv[tid] = (tid == 10) ? 0.f : NEGV;   // START = 10
    __syncthreads();

    if (tid < 32) {
        float tr[12];
        if (tid < 12) {
#pragma unroll
            for (int j = 0; j < 12; j++) tr[j] = transitions[tid * 12 + j];
        }
        for (int t = 0; t < 1024; t++) {
            float best = 0.f, nf = 0.f; int bj = 0;
            if (tid < 12) {
                best = fv[0] + tr[0]; bj = 0;
#pragma unroll
                for (int j = 1; j < 12; j++) {
                    float s = fv[j] + tr[j];
                    if (s > best) { best = s; bj = j; }   // first-max tie-break
                }
                nf = best + feats_s[t * 12 + tid];
            }
            bool m = (t < len);
            __syncwarp();
            if (tid < 12) {
                bp[t * 12 + tid] = (unsigned char)(m ? bj : tid);
                if (m) fv[tid] = nf;
            }
            __syncwarp();
        }
        if (tid == 0) {
            float bestv = -3.4e38f; int bt = 0;
            for (int k = 0; k < 12; k++) {
                float tv = fv[k] + transitions[11 * 12 + k];   // STOP = 11
                if (tv > bestv) { bestv = tv; bt = k; }
            }
            out[b] = bestv;
            float* po = out + 64 + (size_t)b * 1024;
            int tag = bt;
            for (int t = 1023; t >= 0; t--) {
                po[t] = (t < len) ? (float)tag : 0.f;
                tag = bp[t * 12 + tag];
            }
        }
    }
}

extern "C" void kernel_launch(void* const* d_in, const int* in_sizes, int n_in,
                              void* d_out, int out_size) {
    const int*   sent     = (const int*)  d_in[0];
    const int*   seq_lens = (const int*)  d_in[1];
    const float* emb      = (const float*)d_in[2];
    const float* Wih_f    = (const float*)d_in[3];
    const float* Whh_f    = (const float*)d_in[4];
    const float* bih_f    = (const float*)d_in[5];
    const float* bhh_f    = (const float*)d_in[6];
    const float* Wih_b    = (const float*)d_in[7];
    const float* Whh_b    = (const float*)d_in[8];
    const float* bih_b    = (const float*)d_in[9];
    const float* bhh_b    = (const float*)d_in[10];
    const float* Wtag     = (const float*)d_in[11];
    const float* btag     = (const float*)d_in[12];
    const float* trans    = (const float*)d_in[13];
    const float* h0       = (const float*)d_in[14];
    const float* c0       = (const float*)d_in[15];
    float* out = (float*)d_out;
    (void)in_sizes; (void)n_in; (void)out_size;

    cudaFuncSetAttribute(viterbi_kernel,
                         cudaFuncAttributeMaxDynamicSharedMemorySize, 61504);

    prep_kernel<<<512, 256>>>(Wih_f, Wih_b, bih_f, bhh_f, bih_b, bhh_b, h0);
    gemm_kernel<<<dim3(16, 512), 256>>>(sent, emb);
    lstm_kernel<<<128, 256>>>(Whh_f, Whh_b, c0, seq_lens);
    feats_kernel<<<dim3(128, 64), 256>>>(Wtag, btag);
    viterbi_kernel<<<64, 128, 61504>>>(trans, seq_lens, out);
}